// round 1
// baseline (speedup 1.0000x reference)
#include <cuda_runtime.h>
#include <math.h>

#define C_    256
#define T_    8
#define H_    32
#define W_    32
#define L_    4
#define THW_  8192
#define NROWS 256              // L * 64 sample points
#define FEAT_OUT_ELEMS (C_*THW_*L_)   // 2097152

// ---- scratch (device globals; no allocation) ----
__device__ float g_glob[L_*C_];        // glob[l][c]
__device__ float g_samp[NROWS*4*3];    // (row,no) -> ix,iy,iz
__device__ float g_wo[NROWS*4];        // (row,no) -> w_o
__device__ float g_s[NROWS];           // row -> softmax-sum scale

__constant__ int c_tt[4] = {1,3,4,6};
__constant__ int c_hh[4] = {4,12,19,27};

__device__ __forceinline__ int flat_idx(int n){
    int it = n >> 4, ih = (n >> 2) & 3, iw = n & 3;
    return (c_tt[it]*H_ + c_hh[ih])*W_ + c_hh[iw];
}
__device__ __forceinline__ float sigmoidf_(float x){ return 1.0f/(1.0f+expf(-x)); }
__device__ __forceinline__ float invsigf_(float x){
    // x already in [0,1]
    return logf(fmaxf(x,1e-5f)/fmaxf(1.0f-x,1e-5f));
}

// ============================================================
// Kernel 1: glob[l][c] = mean over THW of features[0,c,:,:,:,l]
// features layout: ((c*THW + p)*L + l), so per-c data is 32768 contiguous
// ============================================================
__global__ void glob_kernel(const float* __restrict__ feats){
    int c = blockIdx.x;
    const float4* f4 = reinterpret_cast<const float4*>(feats + (size_t)c * (THW_*L_));
    float4 s = make_float4(0.f,0.f,0.f,0.f);
    for (int i = threadIdx.x; i < THW_; i += 256){
        float4 v = f4[i];
        s.x += v.x; s.y += v.y; s.z += v.z; s.w += v.w;
    }
    __shared__ float4 sm[256];
    sm[threadIdx.x] = s;
    __syncthreads();
    for (int o = 128; o > 0; o >>= 1){
        if (threadIdx.x < o){
            float4 a = sm[threadIdx.x], b = sm[threadIdx.x+o];
            sm[threadIdx.x] = make_float4(a.x+b.x, a.y+b.y, a.z+b.z, a.w+b.w);
        }
        __syncthreads();
    }
    if (threadIdx.x == 0){
        float4 t = sm[0];
        const float inv = 1.0f/8192.0f;
        g_glob[0*C_+c] = t.x*inv;
        g_glob[1*C_+c] = t.y*inv;
        g_glob[2*C_+c] = t.z*inv;
        g_glob[3*C_+c] = t.w*inv;
    }
}

// ============================================================
// Kernel 2: fused MLP + heads. 64 blocks x 256 threads, 4 rows/block.
// Row r = l*64 + n.
// ============================================================
__global__ void mlp_kernel(const float* __restrict__ feats, const float* __restrict__ pos,
    const float* __restrict__ W1, const float* __restrict__ b1,
    const float* __restrict__ W2, const float* __restrict__ b2,
    const float* __restrict__ Wn, const float* __restrict__ bn,
    const float* __restrict__ Wl, const float* __restrict__ bl,
    const float* __restrict__ Woff, const float* __restrict__ boff,
    const float* __restrict__ Ww, const float* __restrict__ bw,
    float* __restrict__ out, int write_next)
{
    __shared__ alignas(16) float X [768*4];   // X[k*4+r]
    __shared__ alignas(16) float H1[256*4];
    __shared__ alignas(16) float H2[256*4];
    __shared__ float HD[4][28];               // [0..2]=nxt [4..7]=wl [8..19]=off [20..27]=wo-z

    int tid = threadIdx.x;
    int r0  = blockIdx.x * 4;

    // ---- gather off_src rows: [feat(256) | pos(256) | glob(256)]
    #pragma unroll
    for (int r = 0; r < 4; r++){
        int rr = r0 + r;
        int l  = rr >> 6;
        int p  = flat_idx(rr & 63);
        for (int k = tid; k < 768; k += 256){
            float v;
            if (k < 256)       v = feats[((size_t)k*THW_ + p)*L_ + l];
            else if (k < 512)  v = pos  [((size_t)(k-256)*THW_ + p)*L_ + l];
            else               v = g_glob[l*C_ + (k-512)];
            X[k*4 + r] = v;
        }
    }
    __syncthreads();

    // ---- layer 1: h1 = relu(X @ W1 + b1), K=768
    {
        int j = tid;
        float a0 = b1[j], a1 = a0, a2 = a0, a3 = a0;
        const float4* X4 = reinterpret_cast<const float4*>(X);
        #pragma unroll 4
        for (int k = 0; k < 768; k++){
            float w = W1[k*256 + j];
            float4 x = X4[k];
            a0 = fmaf(x.x, w, a0); a1 = fmaf(x.y, w, a1);
            a2 = fmaf(x.z, w, a2); a3 = fmaf(x.w, w, a3);
        }
        H1[j*4+0] = fmaxf(a0, 0.f); H1[j*4+1] = fmaxf(a1, 0.f);
        H1[j*4+2] = fmaxf(a2, 0.f); H1[j*4+3] = fmaxf(a3, 0.f);
    }
    __syncthreads();

    // ---- layer 2: h2 = relu(h1 @ W2 + b2), K=256
    {
        int j = tid;
        float a0 = b2[j], a1 = a0, a2 = a0, a3 = a0;
        const float4* H14 = reinterpret_cast<const float4*>(H1);
        #pragma unroll 4
        for (int k = 0; k < 256; k++){
            float w = W2[k*256 + j];
            float4 x = H14[k];
            a0 = fmaf(x.x, w, a0); a1 = fmaf(x.y, w, a1);
            a2 = fmaf(x.z, w, a2); a3 = fmaf(x.w, w, a3);
        }
        H2[j*4+0] = fmaxf(a0, 0.f); H2[j*4+1] = fmaxf(a1, 0.f);
        H2[j*4+2] = fmaxf(a2, 0.f); H2[j*4+3] = fmaxf(a3, 0.f);
    }
    __syncthreads();

    // ---- heads: 64-thread group per row, small serial dots out of smem
    int r = tid >> 6;
    int t = tid & 63;
    if (t < 3){                               // nxt = h2 @ Wn + bn
        float s = bn[t];
        for (int k = 0; k < 256; k++) s = fmaf(H2[k*4 + r], Wn[k*3 + t], s);
        HD[r][t] = s;
    } else if (t >= 4 && t < 8){              // wl logits
        int jl = t - 4;
        float s = bl[jl];
        for (int k = 0; k < 256; k++) s = fmaf(H2[k*4 + r], Wl[k*4 + jl], s);
        HD[r][t] = s;
    } else if (t >= 8 && t < 20){             // offsets: no in 0..3, jo in 0..2 over h2[no*64:+64]
        int u = t - 8;
        int no = u / 3, jo = u - no*3;
        float s = boff[jo];
        for (int dd = 0; dd < 64; dd++) s = fmaf(H2[(no*64+dd)*4 + r], Woff[dd*3 + jo], s);
        HD[r][8+u] = s;
    } else if (t >= 20 && t < 28){            // w_o logits z0,z1 per no
        int u = t - 20;
        int no = u >> 1, comp = u & 1;
        float s = bw[comp];
        for (int dd = 0; dd < 64; dd++) s = fmaf(H2[(no*64+dd)*4 + r], Ww[dd*2 + comp], s);
        HD[r][20+u] = s;
    }
    __syncthreads();

    if (t == 0){
        int rr = r0 + r;
        int l  = rr >> 6;   (void)l;
        int p  = flat_idx(rr & 63);
        int tq = p >> 10, hq = (p >> 5) & 31, wq = p & 31;
        float tn = (float)tq * (1.0f/7.0f);
        float hn = (float)hq * (1.0f/31.0f);
        float wn = (float)wq * (1.0f/31.0f);
        float ivt = invsigf_(tn), ivh = invsigf_(hn), ivw = invsigf_(wn);

        // wl softmax row-sum (scale s, ~1.0)
        float z0 = HD[r][4], z1 = HD[r][5], z2 = HD[r][6], z3 = HD[r][7];
        float m  = fmaxf(fmaxf(z0,z1), fmaxf(z2,z3));
        float e0 = expf(z0-m), e1 = expf(z1-m), e2 = expf(z2-m), e3 = expf(z3-m);
        float S  = e0+e1+e2+e3;
        g_s[rr]  = e0/S + e1/S + e2/S + e3/S;

        #pragma unroll
        for (int no = 0; no < 4; no++){
            float o0 = HD[r][8+no*3+0], o1 = HD[r][8+no*3+1], o2 = HD[r][8+no*3+2];
            float st = sigmoidf_(ivt + o0)*2.0f - 1.0f;
            float sh = sigmoidf_(ivh + o1)*2.0f - 1.0f;
            float sw = sigmoidf_(ivw + o2)*2.0f - 1.0f;
            // grid_sample: ch0 -> x over W=32, ch1 -> y over H=32, ch2 -> z over D=T=8
            float ix = ((st + 1.0f)*32.0f - 1.0f)*0.5f;
            float iy = ((sh + 1.0f)*32.0f - 1.0f)*0.5f;
            float iz = ((sw + 1.0f)*8.0f  - 1.0f)*0.5f;
            int bidx = (rr*4 + no)*3;
            g_samp[bidx+0] = ix; g_samp[bidx+1] = iy; g_samp[bidx+2] = iz;
            float za = HD[r][20+no*2], zb = HD[r][21+no*2];
            g_wo[rr*4 + no] = 1.0f/(1.0f + expf(za - zb));   // softmax[...,1]
        }

        if (write_next){
            float d0 = sigmoidf_(ivt + HD[r][0]) * 7.0f;
            float d1 = sigmoidf_(ivh + HD[r][1]) * 31.0f;
            float d2 = sigmoidf_(ivw + HD[r][2]) * 31.0f;
            int ni = 1024*(int)rintf(d0) + 32*(int)rintf(d1) + (int)rintf(d2);
            out[FEAT_OUT_ELEMS + rr] = (float)ni;
        }
    }
}

// ============================================================
// Kernel 3: fill everything with beta[c] (layernorm of a zero vector)
// out layout (c*THW + p)*L + l -> one float4 per (c,p) spans the 4 l's
// ============================================================
__global__ void fill_kernel(const float* __restrict__ beta, float4* __restrict__ out){
    int i = blockIdx.x * blockDim.x + threadIdx.x;      // 524288 float4s
    float b = __ldg(&beta[i >> 13]);                    // c = i / 8192
    out[i] = make_float4(b, b, b, b);
}

// ============================================================
// Kernel 4: for each of 256 (l,n) sampled columns:
//   v[c] = (features[c,p,l] + sum_no wo * trilinear(features[:,c,:,l])) * s
//   out[c,p,l] = LN_C(v) * gamma + beta
// ============================================================
__global__ void sample_ln_kernel(const float* __restrict__ feats,
                                 const float* __restrict__ gamma,
                                 const float* __restrict__ beta,
                                 float* __restrict__ out)
{
    int b  = blockIdx.x;           // row = l*64 + n
    int l  = b >> 6;
    int p  = flat_idx(b & 63);
    int tid = threadIdx.x;

    __shared__ int   qs[32];
    __shared__ float ws[32];
    __shared__ float red[256];
    __shared__ float s_scale, s_mu, s_var;

    if (tid < 4){
        int no = tid;
        int gi = (b*4 + no)*3;
        float ix = g_samp[gi+0], iy = g_samp[gi+1], iz = g_samp[gi+2];
        float wo = g_wo[b*4 + no];
        float x0f = floorf(ix), y0f = floorf(iy), z0f = floorf(iz);
        int   x0 = (int)x0f, y0 = (int)y0f, z0 = (int)z0f;
        float fx = ix - x0f, fy = iy - y0f, fz = iz - z0f;
        #pragma unroll
        for (int j = 0; j < 8; j++){
            int dx = j & 1, dy = (j >> 1) & 1, dz = j >> 2;
            int xi = x0 + dx, yi = y0 + dy, zi = z0 + dz;
            float w = (dx ? fx : 1.0f-fx) * (dy ? fy : 1.0f-fy) * (dz ? fz : 1.0f-fz);
            bool valid = (xi >= 0) & (xi < W_) & (yi >= 0) & (yi < H_) & (zi >= 0) & (zi < T_);
            int xc = min(max(xi,0),W_-1), yc = min(max(yi,0),H_-1), zc = min(max(zi,0),T_-1);
            qs[no*8 + j] = (zc*H_ + yc)*W_ + xc;
            ws[no*8 + j] = valid ? w*wo : 0.0f;
        }
    }
    if (tid == 0) s_scale = g_s[b];
    __syncthreads();

    int c = tid;
    float v = feats[((size_t)c*THW_ + p)*L_ + l];
    float acc = 0.0f;
    #pragma unroll 8
    for (int j = 0; j < 32; j++){
        acc = fmaf(ws[j], feats[((size_t)c*THW_ + qs[j])*L_ + l], acc);
    }
    v = (v + acc) * s_scale;

    // mean
    red[tid] = v; __syncthreads();
    for (int o = 128; o > 0; o >>= 1){
        if (tid < o) red[tid] += red[tid + o];
        __syncthreads();
    }
    if (tid == 0) s_mu = red[0] * (1.0f/256.0f);
    __syncthreads();
    float d = v - s_mu;
    red[tid] = d*d; __syncthreads();
    for (int o = 128; o > 0; o >>= 1){
        if (tid < o) red[tid] += red[tid + o];
        __syncthreads();
    }
    if (tid == 0) s_var = red[0] * (1.0f/256.0f);
    __syncthreads();

    float o = d * rsqrtf(s_var + 1e-5f) * gamma[c] + beta[c];
    out[((size_t)c*THW_ + p)*L_ + l] = o;
}

// ============================================================
extern "C" void kernel_launch(void* const* d_in, const int* in_sizes, int n_in,
                              void* d_out, int out_size)
{
    const float* feats = (const float*)d_in[0];
    const float* pos   = (const float*)d_in[1];
    const float* W1    = (const float*)d_in[2];
    const float* b1    = (const float*)d_in[3];
    const float* W2    = (const float*)d_in[4];
    const float* b2    = (const float*)d_in[5];
    const float* Wn    = (const float*)d_in[6];
    const float* bn    = (const float*)d_in[7];
    const float* Wl    = (const float*)d_in[8];
    const float* bl    = (const float*)d_in[9];
    const float* Woff  = (const float*)d_in[10];
    const float* boff  = (const float*)d_in[11];
    const float* Ww    = (const float*)d_in[12];
    const float* bw    = (const float*)d_in[13];
    const float* gamma = (const float*)d_in[14];
    const float* beta  = (const float*)d_in[15];
    float* out = (float*)d_out;

    int write_next = (out_size >= FEAT_OUT_ELEMS + NROWS) ? 1 : 0;

    glob_kernel<<<256, 256>>>(feats);
    mlp_kernel<<<64, 256>>>(feats, pos, W1, b1, W2, b2, Wn, bn, Wl, bl,
                            Woff, boff, Ww, bw, out, write_next);
    fill_kernel<<<2048, 256>>>(beta, (float4*)out);
    sample_ln_kernel<<<256, 256>>>(feats, gamma, beta, out);
}

// round 2
// speedup vs baseline: 1.3406x; 1.3406x over previous
#include <cuda_runtime.h>
#include <math.h>

#define C_    256
#define T_    8
#define H_    32
#define W_    32
#define L_    4
#define THW_  8192
#define NROWS 256              // L * 64 sample points
#define FEAT_OUT_ELEMS (C_*THW_*L_)   // 2097152

// ---- scratch (device globals; no allocation) ----
__device__ float g_glob[L_*C_];        // glob[l][c]
__device__ float g_samp[NROWS*4*3];    // (row,no) -> ix,iy,iz
__device__ float g_wo[NROWS*4];        // (row,no) -> w_o
__device__ float g_s[NROWS];           // row -> softmax-sum scale

__constant__ int c_tt[4] = {1,3,4,6};
__constant__ int c_hh[4] = {4,12,19,27};

__device__ __forceinline__ int flat_idx(int n){
    int it = n >> 4, ih = (n >> 2) & 3, iw = n & 3;
    return (c_tt[it]*H_ + c_hh[ih])*W_ + c_hh[iw];
}
__device__ __forceinline__ float sigmoidf_(float x){ return 1.0f/(1.0f+expf(-x)); }
__device__ __forceinline__ float invsigf_(float x){
    return logf(fmaxf(x,1e-5f)/fmaxf(1.0f-x,1e-5f));
}
__device__ __forceinline__ void cp_async16(void* smem_dst, const void* gmem_src){
    unsigned s = (unsigned)__cvta_generic_to_shared(smem_dst);
    asm volatile("cp.async.cg.shared.global [%0], [%1], 16;\n" :: "r"(s), "l"(gmem_src));
}
__device__ __forceinline__ void cp_commit(){ asm volatile("cp.async.commit_group;\n"); }
__device__ __forceinline__ void cp_wait0(){ asm volatile("cp.async.wait_group 0;\n"); }
__device__ __forceinline__ void cp_wait1(){ asm volatile("cp.async.wait_group 1;\n"); }

// ============================================================
// Kernel 1: glob[l][c] = mean over THW of features[0,c,:,:,:,l]
// ============================================================
__global__ void glob_kernel(const float* __restrict__ feats){
    int c = blockIdx.x;
    const float4* f4 = reinterpret_cast<const float4*>(feats + (size_t)c * (THW_*L_));
    float4 s = make_float4(0.f,0.f,0.f,0.f);
    for (int i = threadIdx.x; i < THW_; i += 256){
        float4 v = f4[i];
        s.x += v.x; s.y += v.y; s.z += v.z; s.w += v.w;
    }
    __shared__ float4 sm[256];
    sm[threadIdx.x] = s;
    __syncthreads();
    for (int o = 128; o > 0; o >>= 1){
        if (threadIdx.x < o){
            float4 a = sm[threadIdx.x], b = sm[threadIdx.x+o];
            sm[threadIdx.x] = make_float4(a.x+b.x, a.y+b.y, a.z+b.z, a.w+b.w);
        }
        __syncthreads();
    }
    if (threadIdx.x == 0){
        float4 t = sm[0];
        const float inv = 1.0f/8192.0f;
        g_glob[0*C_+c] = t.x*inv;
        g_glob[1*C_+c] = t.y*inv;
        g_glob[2*C_+c] = t.z*inv;
        g_glob[3*C_+c] = t.w*inv;
    }
}

// ============================================================
// Kernel 2: fused MLP + heads. 64 blocks x 256 threads, 4 rows/block.
// Weights streamed via cp.async double-buffered smem tiles (Kt=64).
// Dynamic smem layout (floats):
//   Xs [768*4]        @ 0
//   H1 [1024]         @ 3072
//   H2 [1024]         @ 4096
//   Wb [2][64*256]    @ 5120
// total = 5120 + 32768 = 37888 floats = 151552 bytes
// ============================================================
#define KT 64
#define SM_XS 0
#define SM_H1 3072
#define SM_H2 4096
#define SM_WB 5120
#define MLP_SMEM_BYTES (37888*4)

__global__ void mlp_kernel(const float* __restrict__ feats, const float* __restrict__ pos,
    const float* __restrict__ W1, const float* __restrict__ b1,
    const float* __restrict__ W2, const float* __restrict__ b2,
    const float* __restrict__ Wn, const float* __restrict__ bn,
    const float* __restrict__ Wl, const float* __restrict__ bl,
    const float* __restrict__ Woff, const float* __restrict__ boff,
    const float* __restrict__ Ww, const float* __restrict__ bw,
    float* __restrict__ out, int write_next)
{
    extern __shared__ float smem[];
    float* Xs = smem + SM_XS;
    float* H1 = smem + SM_H1;
    float* H2 = smem + SM_H2;
    float* Wb0 = smem + SM_WB;
    float* Wb1 = smem + SM_WB + KT*256;
    __shared__ float HD[4][28];

    int tid = threadIdx.x;
    int r0  = blockIdx.x * 4;

    // ---- kick off prefetch of W1 tile 0 immediately
    const float4* W1v = reinterpret_cast<const float4*>(W1);   // [768*64] float4
    {
        #pragma unroll
        for (int u = 0; u < 16; u++)
            cp_async16((float4*)Wb0 + tid + u*256, W1v + tid + u*256);
        cp_commit();
    }

    // ---- gather off_src rows: [feat(256) | pos(256) | glob(256)], X[k*4+r]
    #pragma unroll
    for (int r = 0; r < 4; r++){
        int rr = r0 + r;
        int l  = rr >> 6;
        int p  = flat_idx(rr & 63);
        for (int k = tid; k < 768; k += 256){
            float v;
            if (k < 256)       v = feats[((size_t)k*THW_ + p)*L_ + l];
            else if (k < 512)  v = pos  [((size_t)(k-256)*THW_ + p)*L_ + l];
            else               v = g_glob[l*C_ + (k-512)];
            Xs[k*4 + r] = v;
        }
    }
    __syncthreads();

    // ---- layer 1: h1 = relu(X @ W1 + b1), K=768, 12 tiles of 64
    {
        int j = tid;
        float a0 = b1[j], a1 = a0, a2 = a0, a3 = a0;
        const float4* X4 = reinterpret_cast<const float4*>(Xs);
        #pragma unroll 1
        for (int t = 0; t < 12; t++){
            float* Wcur = (t & 1) ? Wb1 : Wb0;
            float* Wnxt = (t & 1) ? Wb0 : Wb1;
            if (t + 1 < 12){
                const float4* src = W1v + (t+1)*4096;
                #pragma unroll
                for (int u = 0; u < 16; u++)
                    cp_async16((float4*)Wnxt + tid + u*256, src + tid + u*256);
                cp_commit();
                cp_wait1();
            } else {
                cp_wait0();
            }
            __syncthreads();
            #pragma unroll 8
            for (int k = 0; k < KT; k++){
                float w = Wcur[k*256 + j];
                float4 x = X4[t*KT + k];
                a0 = fmaf(x.x, w, a0); a1 = fmaf(x.y, w, a1);
                a2 = fmaf(x.z, w, a2); a3 = fmaf(x.w, w, a3);
            }
            __syncthreads();
        }
        H1[j*4+0] = fmaxf(a0, 0.f); H1[j*4+1] = fmaxf(a1, 0.f);
        H1[j*4+2] = fmaxf(a2, 0.f); H1[j*4+3] = fmaxf(a3, 0.f);
    }
    __syncthreads();

    // ---- layer 2: h2 = relu(h1 @ W2 + b2), K=256, 4 tiles of 64
    {
        const float4* W2v = reinterpret_cast<const float4*>(W2);
        // prefetch tile 0
        #pragma unroll
        for (int u = 0; u < 16; u++)
            cp_async16((float4*)Wb0 + tid + u*256, W2v + tid + u*256);
        cp_commit();

        int j = tid;
        float a0 = b2[j], a1 = a0, a2 = a0, a3 = a0;
        const float4* X4 = reinterpret_cast<const float4*>(H1);
        #pragma unroll 1
        for (int t = 0; t < 4; t++){
            float* Wcur = (t & 1) ? Wb1 : Wb0;
            float* Wnxt = (t & 1) ? Wb0 : Wb1;
            if (t + 1 < 4){
                const float4* src = W2v + (t+1)*4096;
                #pragma unroll
                for (int u = 0; u < 16; u++)
                    cp_async16((float4*)Wnxt + tid + u*256, src + tid + u*256);
                cp_commit();
                cp_wait1();
            } else {
                cp_wait0();
            }
            __syncthreads();
            #pragma unroll 8
            for (int k = 0; k < KT; k++){
                float w = Wcur[k*256 + j];
                float4 x = X4[t*KT + k];
                a0 = fmaf(x.x, w, a0); a1 = fmaf(x.y, w, a1);
                a2 = fmaf(x.z, w, a2); a3 = fmaf(x.w, w, a3);
            }
            __syncthreads();
        }
        H2[j*4+0] = fmaxf(a0, 0.f); H2[j*4+1] = fmaxf(a1, 0.f);
        H2[j*4+2] = fmaxf(a2, 0.f); H2[j*4+3] = fmaxf(a3, 0.f);
    }
    __syncthreads();

    // ---- heads
    int r = tid >> 6;
    int t = tid & 63;
    if (t < 3){                               // nxt
        float s = bn[t];
        #pragma unroll 8
        for (int k = 0; k < 256; k++) s = fmaf(H2[k*4 + r], Wn[k*3 + t], s);
        HD[r][t] = s;
    } else if (t >= 4 && t < 8){              // wl logits
        int jl = t - 4;
        float s = bl[jl];
        #pragma unroll 8
        for (int k = 0; k < 256; k++) s = fmaf(H2[k*4 + r], Wl[k*4 + jl], s);
        HD[r][t] = s;
    } else if (t >= 8 && t < 20){             // offsets
        int u = t - 8;
        int no = u / 3, jo = u - no*3;
        float s = boff[jo];
        #pragma unroll 8
        for (int dd = 0; dd < 64; dd++) s = fmaf(H2[(no*64+dd)*4 + r], Woff[dd*3 + jo], s);
        HD[r][8+u] = s;
    } else if (t >= 20 && t < 28){            // w_o logits
        int u = t - 20;
        int no = u >> 1, comp = u & 1;
        float s = bw[comp];
        #pragma unroll 8
        for (int dd = 0; dd < 64; dd++) s = fmaf(H2[(no*64+dd)*4 + r], Ww[dd*2 + comp], s);
        HD[r][20+u] = s;
    }
    __syncthreads();

    if (t == 0){
        int rr = r0 + r;
        int p  = flat_idx(rr & 63);
        int tq = p >> 10, hq = (p >> 5) & 31, wq = p & 31;
        float tn = (float)tq * (1.0f/7.0f);
        float hn = (float)hq * (1.0f/31.0f);
        float wn = (float)wq * (1.0f/31.0f);
        float ivt = invsigf_(tn), ivh = invsigf_(hn), ivw = invsigf_(wn);

        float z0 = HD[r][4], z1 = HD[r][5], z2 = HD[r][6], z3 = HD[r][7];
        float m  = fmaxf(fmaxf(z0,z1), fmaxf(z2,z3));
        float e0 = expf(z0-m), e1 = expf(z1-m), e2 = expf(z2-m), e3 = expf(z3-m);
        float S  = e0+e1+e2+e3;
        g_s[rr]  = e0/S + e1/S + e2/S + e3/S;

        #pragma unroll
        for (int no = 0; no < 4; no++){
            float o0 = HD[r][8+no*3+0], o1 = HD[r][8+no*3+1], o2 = HD[r][8+no*3+2];
            float st = sigmoidf_(ivt + o0)*2.0f - 1.0f;
            float sh = sigmoidf_(ivh + o1)*2.0f - 1.0f;
            float sw = sigmoidf_(ivw + o2)*2.0f - 1.0f;
            float ix = ((st + 1.0f)*32.0f - 1.0f)*0.5f;
            float iy = ((sh + 1.0f)*32.0f - 1.0f)*0.5f;
            float iz = ((sw + 1.0f)*8.0f  - 1.0f)*0.5f;
            int bidx = (rr*4 + no)*3;
            g_samp[bidx+0] = ix; g_samp[bidx+1] = iy; g_samp[bidx+2] = iz;
            float za = HD[r][20+no*2], zb = HD[r][21+no*2];
            g_wo[rr*4 + no] = 1.0f/(1.0f + expf(za - zb));
        }

        if (write_next){
            float d0 = sigmoidf_(ivt + HD[r][0]) * 7.0f;
            float d1 = sigmoidf_(ivh + HD[r][1]) * 31.0f;
            float d2 = sigmoidf_(ivw + HD[r][2]) * 31.0f;
            int ni = 1024*(int)rintf(d0) + 32*(int)rintf(d1) + (int)rintf(d2);
            out[FEAT_OUT_ELEMS + rr] = (float)ni;
        }
    }
}

// ============================================================
// Kernel 3: fill everything with beta[c]
// ============================================================
__global__ void fill_kernel(const float* __restrict__ beta, float4* __restrict__ out){
    int i = blockIdx.x * blockDim.x + threadIdx.x;      // 524288 float4s
    float b = __ldg(&beta[i >> 13]);
    out[i] = make_float4(b, b, b, b);
}

// ============================================================
// Kernel 4: 256 blocks x 512 threads. Two half-sums per channel.
// ============================================================
__global__ void sample_ln_kernel(const float* __restrict__ feats,
                                 const float* __restrict__ gamma,
                                 const float* __restrict__ beta,
                                 float* __restrict__ out)
{
    int b  = blockIdx.x;           // row = l*64 + n
    int l  = b >> 6;
    int p  = flat_idx(b & 63);
    int tid = threadIdx.x;

    __shared__ int    qs[32];
    __shared__ float  ws[32];
    __shared__ float  partial[256];
    __shared__ float2 red[512];
    __shared__ float  s_scale, s_mu, s_rstd;

    if (tid < 4){
        int no = tid;
        int gi = (b*4 + no)*3;
        float ix = g_samp[gi+0], iy = g_samp[gi+1], iz = g_samp[gi+2];
        float wo = g_wo[b*4 + no];
        float x0f = floorf(ix), y0f = floorf(iy), z0f = floorf(iz);
        int   x0 = (int)x0f, y0 = (int)y0f, z0 = (int)z0f;
        float fx = ix - x0f, fy = iy - y0f, fz = iz - z0f;
        #pragma unroll
        for (int j = 0; j < 8; j++){
            int dx = j & 1, dy = (j >> 1) & 1, dz = j >> 2;
            int xi = x0 + dx, yi = y0 + dy, zi = z0 + dz;
            float w = (dx ? fx : 1.0f-fx) * (dy ? fy : 1.0f-fy) * (dz ? fz : 1.0f-fz);
            bool valid = (xi >= 0) & (xi < W_) & (yi >= 0) & (yi < H_) & (zi >= 0) & (zi < T_);
            int xc = min(max(xi,0),W_-1), yc = min(max(yi,0),H_-1), zc = min(max(zi,0),T_-1);
            qs[no*8 + j] = (zc*H_ + yc)*W_ + xc;
            ws[no*8 + j] = valid ? w*wo : 0.0f;
        }
    }
    if (tid == 0) s_scale = g_s[b];
    __syncthreads();

    int c    = tid & 255;
    int half = tid >> 8;
    const float* fb = feats + (size_t)c*(THW_*L_) + l;

    float acc = 0.0f;
    int j0 = half * 16;
    #pragma unroll
    for (int j = 0; j < 16; j++)
        acc = fmaf(ws[j0+j], __ldg(fb + (size_t)qs[j0+j]*L_), acc);
    if (half == 0) acc += __ldg(fb + (size_t)p*L_);   // residual

    if (half) partial[c] = acc;
    __syncthreads();

    float v = 0.0f;
    if (half == 0) v = (acc + partial[c]) * s_scale;

    // fused mean / sumsq reduction over 512 entries (upper half contributes 0)
    red[tid] = make_float2(v, v*v);
    __syncthreads();
    for (int o = 256; o > 0; o >>= 1){
        if (tid < o){
            float2 a = red[tid], bb = red[tid+o];
            red[tid] = make_float2(a.x+bb.x, a.y+bb.y);
        }
        __syncthreads();
    }
    if (tid == 0){
        float mu = red[0].x * (1.0f/256.0f);
        float var = red[0].y * (1.0f/256.0f) - mu*mu;
        s_mu = mu;
        s_rstd = rsqrtf(var + 1e-5f);
    }
    __syncthreads();

    if (half == 0){
        float o = (v - s_mu) * s_rstd * gamma[c] + beta[c];
        out[((size_t)c*THW_ + p)*L_ + l] = o;
    }
}

// ============================================================
extern "C" void kernel_launch(void* const* d_in, const int* in_sizes, int n_in,
                              void* d_out, int out_size)
{
    const float* feats = (const float*)d_in[0];
    const float* pos   = (const float*)d_in[1];
    const float* W1    = (const float*)d_in[2];
    const float* b1    = (const float*)d_in[3];
    const float* W2    = (const float*)d_in[4];
    const float* b2    = (const float*)d_in[5];
    const float* Wn    = (const float*)d_in[6];
    const float* bn    = (const float*)d_in[7];
    const float* Wl    = (const float*)d_in[8];
    const float* bl    = (const float*)d_in[9];
    const float* Woff  = (const float*)d_in[10];
    const float* boff  = (const float*)d_in[11];
    const float* Ww    = (const float*)d_in[12];
    const float* bw    = (const float*)d_in[13];
    const float* gamma = (const float*)d_in[14];
    const float* beta  = (const float*)d_in[15];
    float* out = (float*)d_out;

    int write_next = (out_size >= FEAT_OUT_ELEMS + NROWS) ? 1 : 0;

    static int smem_set = 0;
    if (!smem_set){
        cudaFuncSetAttribute(mlp_kernel, cudaFuncAttributeMaxDynamicSharedMemorySize,
                             MLP_SMEM_BYTES);
        smem_set = 1;
    }

    glob_kernel<<<256, 256>>>(feats);
    fill_kernel<<<2048, 256>>>(beta, (float4*)out);
    mlp_kernel<<<64, 256, MLP_SMEM_BYTES>>>(feats, pos, W1, b1, W2, b2, Wn, bn, Wl, bl,
                                            Woff, boff, Ww, bw, out, write_next);
    sample_ln_kernel<<<256, 512>>>(feats, gamma, beta, out);
}

// round 3
// speedup vs baseline: 1.7829x; 1.3299x over previous
#include <cuda_runtime.h>
#include <math.h>

#define C_    256
#define T_    8
#define H_    32
#define W_    32
#define L_    4
#define THW_  8192
#define NROWS 256              // L * 64 sample points
#define FEAT_OUT_ELEMS (C_*THW_*L_)   // 2097152

// ---- scratch (device globals; no allocation) ----
__device__ float g_glob[L_*C_];        // glob[l][c]
__device__ float g_samp[NROWS*4*3];    // (row,no) -> ix,iy,iz
__device__ float g_wo[NROWS*4];        // (row,no) -> w_o
__device__ float g_s[NROWS];           // row -> softmax-sum scale

__constant__ int c_tt[4] = {1,3,4,6};
__constant__ int c_hh[4] = {4,12,19,27};

__device__ __forceinline__ int flat_idx(int n){
    int it = n >> 4, ih = (n >> 2) & 3, iw = n & 3;
    return (c_tt[it]*H_ + c_hh[ih])*W_ + c_hh[iw];
}
__device__ __forceinline__ float sigmoidf_(float x){ return 1.0f/(1.0f+expf(-x)); }
__device__ __forceinline__ float invsigf_(float x){
    return logf(fmaxf(x,1e-5f)/fmaxf(1.0f-x,1e-5f));
}
__device__ __forceinline__ void cp_async16(void* smem_dst, const void* gmem_src){
    unsigned s = (unsigned)__cvta_generic_to_shared(smem_dst);
    asm volatile("cp.async.cg.shared.global [%0], [%1], 16;\n" :: "r"(s), "l"(gmem_src));
}
__device__ __forceinline__ void cp_commit(){ asm volatile("cp.async.commit_group;\n"); }
__device__ __forceinline__ void cp_wait0(){ asm volatile("cp.async.wait_group 0;\n"); }
__device__ __forceinline__ void cp_wait1(){ asm volatile("cp.async.wait_group 1;\n"); }

// ============================================================
// Kernel 1: glob[l][c] = mean over THW of features[0,c,:,:,:,l]
// ============================================================
__global__ void glob_kernel(const float* __restrict__ feats){
    int c = blockIdx.x;
    const float4* f4 = reinterpret_cast<const float4*>(feats + (size_t)c * (THW_*L_));
    float4 s = make_float4(0.f,0.f,0.f,0.f);
    for (int i = threadIdx.x; i < THW_; i += 256){
        float4 v = f4[i];
        s.x += v.x; s.y += v.y; s.z += v.z; s.w += v.w;
    }
    __shared__ float4 sm[256];
    sm[threadIdx.x] = s;
    __syncthreads();
    for (int o = 128; o > 0; o >>= 1){
        if (threadIdx.x < o){
            float4 a = sm[threadIdx.x], b = sm[threadIdx.x+o];
            sm[threadIdx.x] = make_float4(a.x+b.x, a.y+b.y, a.z+b.z, a.w+b.w);
        }
        __syncthreads();
    }
    if (threadIdx.x == 0){
        float4 t = sm[0];
        const float inv = 1.0f/8192.0f;
        g_glob[0*C_+c] = t.x*inv;
        g_glob[1*C_+c] = t.y*inv;
        g_glob[2*C_+c] = t.z*inv;
        g_glob[3*C_+c] = t.w*inv;
    }
}

// ============================================================
// Kernel 2: fused MLP + heads. 128 blocks x 256 threads, 2 rows/block.
// Dynamic smem layout (floats):
//   Xs  [768*2]   @ 0      (1536)
//   H1  [256*2]   @ 1536   (512)
//   H2  [256*2]   @ 2048   (512)
//   HWn [768]     @ 2560
//   HWl [1024]    @ 3328
//   HWof[192]     @ 4352
//   HWw [128]     @ 4544
//   Wb  [2][16384]@ 4672
// total = 4672 + 32768 = 37440 floats = 149760 bytes
// ============================================================
#define KT 64
#define SM_XS  0
#define SM_H1  1536
#define SM_H2  2048
#define SM_WN  2560
#define SM_WL  3328
#define SM_WOF 4352
#define SM_WW  4544
#define SM_WB  4672
#define MLP_SMEM_BYTES (37440*4)

__global__ void mlp_kernel(const float* __restrict__ feats, const float* __restrict__ pos,
    const float* __restrict__ W1, const float* __restrict__ b1,
    const float* __restrict__ W2, const float* __restrict__ b2,
    const float* __restrict__ Wn, const float* __restrict__ bn,
    const float* __restrict__ Wl, const float* __restrict__ bl,
    const float* __restrict__ Woff, const float* __restrict__ boff,
    const float* __restrict__ Ww, const float* __restrict__ bw,
    float* __restrict__ out, int write_next)
{
    extern __shared__ float smem[];
    float* Xs  = smem + SM_XS;
    float* H1  = smem + SM_H1;
    float* H2  = smem + SM_H2;
    float* HWn = smem + SM_WN;
    float* HWl = smem + SM_WL;
    float* HWo = smem + SM_WOF;
    float* HWw = smem + SM_WW;
    float* Wb0 = smem + SM_WB;
    float* Wb1 = smem + SM_WB + KT*256;
    __shared__ float HD[2][28];

    int tid = threadIdx.x;
    int r0  = blockIdx.x * 2;
    int l   = r0 >> 6;          // both rows share l (r0 even)

    // ---- kick off prefetch of W1 tile 0 immediately
    const float4* W1v = reinterpret_cast<const float4*>(W1);
    {
        #pragma unroll
        for (int u = 0; u < 16; u++)
            cp_async16((float4*)Wb0 + tid + u*256, W1v + tid + u*256);
        cp_commit();
    }

    // ---- gather off_src rows into Xs[k*2+r]
    #pragma unroll
    for (int r = 0; r < 2; r++){
        int p = flat_idx((r0 + r) & 63);
        for (int k = tid; k < 768; k += 256){
            float v;
            if (k < 256)       v = feats[((size_t)k*THW_ + p)*L_ + l];
            else if (k < 512)  v = pos  [((size_t)(k-256)*THW_ + p)*L_ + l];
            else               v = g_glob[l*C_ + (k-512)];
            Xs[k*2 + r] = v;
        }
    }
    // ---- preload head weights into smem (coalesced)
    for (int k = tid; k < 768;  k += 256) HWn[k] = Wn[k];
    for (int k = tid; k < 1024; k += 256) HWl[k] = Wl[k];
    if (tid < 192) HWo[tid] = Woff[tid];
    if (tid < 128) HWw[tid] = Ww[tid];
    __syncthreads();

    // ---- layer 1: K=768, 12 tiles of 64
    {
        int j = tid;
        float a0 = b1[j], a1 = a0;
        const float2* X2 = reinterpret_cast<const float2*>(Xs);
        #pragma unroll 1
        for (int t = 0; t < 12; t++){
            float* Wcur = (t & 1) ? Wb1 : Wb0;
            float* Wnxt = (t & 1) ? Wb0 : Wb1;
            if (t + 1 < 12){
                const float4* src = W1v + (t+1)*4096;
                #pragma unroll
                for (int u = 0; u < 16; u++)
                    cp_async16((float4*)Wnxt + tid + u*256, src + tid + u*256);
                cp_commit();
                cp_wait1();
            } else {
                cp_wait0();
            }
            __syncthreads();
            #pragma unroll 8
            for (int k = 0; k < KT; k++){
                float w = Wcur[k*256 + j];
                float2 x = X2[t*KT + k];
                a0 = fmaf(x.x, w, a0); a1 = fmaf(x.y, w, a1);
            }
            __syncthreads();
        }
        H1[j*2+0] = fmaxf(a0, 0.f); H1[j*2+1] = fmaxf(a1, 0.f);
    }
    __syncthreads();

    // ---- layer 2: K=256, 4 tiles of 64
    {
        const float4* W2v = reinterpret_cast<const float4*>(W2);
        #pragma unroll
        for (int u = 0; u < 16; u++)
            cp_async16((float4*)Wb0 + tid + u*256, W2v + tid + u*256);
        cp_commit();

        int j = tid;
        float a0 = b2[j], a1 = a0;
        const float2* X2 = reinterpret_cast<const float2*>(H1);
        #pragma unroll 1
        for (int t = 0; t < 4; t++){
            float* Wcur = (t & 1) ? Wb1 : Wb0;
            float* Wnxt = (t & 1) ? Wb0 : Wb1;
            if (t + 1 < 4){
                const float4* src = W2v + (t+1)*4096;
                #pragma unroll
                for (int u = 0; u < 16; u++)
                    cp_async16((float4*)Wnxt + tid + u*256, src + tid + u*256);
                cp_commit();
                cp_wait1();
            } else {
                cp_wait0();
            }
            __syncthreads();
            #pragma unroll 8
            for (int k = 0; k < KT; k++){
                float w = Wcur[k*256 + j];
                float2 x = X2[t*KT + k];
                a0 = fmaf(x.x, w, a0); a1 = fmaf(x.y, w, a1);
            }
            __syncthreads();
        }
        H2[j*2+0] = fmaxf(a0, 0.f); H2[j*2+1] = fmaxf(a1, 0.f);
    }
    __syncthreads();

    // ---- heads: 128 threads per row, all weight reads from smem
    int r = tid >> 7;
    int t = tid & 127;
    if (t < 3){                               // nxt
        float s = bn[t];
        #pragma unroll 8
        for (int k = 0; k < 256; k++) s = fmaf(H2[k*2 + r], HWn[k*3 + t], s);
        HD[r][t] = s;
    } else if (t >= 4 && t < 8){              // wl logits
        int jl = t - 4;
        float s = bl[jl];
        #pragma unroll 8
        for (int k = 0; k < 256; k++) s = fmaf(H2[k*2 + r], HWl[k*4 + jl], s);
        HD[r][t] = s;
    } else if (t >= 8 && t < 20){             // offsets
        int u = t - 8;
        int no = u / 3, jo = u - no*3;
        float s = boff[jo];
        #pragma unroll 8
        for (int dd = 0; dd < 64; dd++) s = fmaf(H2[(no*64+dd)*2 + r], HWo[dd*3 + jo], s);
        HD[r][8+u] = s;
    } else if (t >= 20 && t < 28){            // w_o logits
        int u = t - 20;
        int no = u >> 1, comp = u & 1;
        float s = bw[comp];
        #pragma unroll 8
        for (int dd = 0; dd < 64; dd++) s = fmaf(H2[(no*64+dd)*2 + r], HWw[dd*2 + comp], s);
        HD[r][20+u] = s;
    }
    __syncthreads();

    if (t == 0){
        int rr = r0 + r;
        int p  = flat_idx(rr & 63);
        int tq = p >> 10, hq = (p >> 5) & 31, wq = p & 31;
        float tn = (float)tq * (1.0f/7.0f);
        float hn = (float)hq * (1.0f/31.0f);
        float wn = (float)wq * (1.0f/31.0f);
        float ivt = invsigf_(tn), ivh = invsigf_(hn), ivw = invsigf_(wn);

        float z0 = HD[r][4], z1 = HD[r][5], z2 = HD[r][6], z3 = HD[r][7];
        float m  = fmaxf(fmaxf(z0,z1), fmaxf(z2,z3));
        float e0 = expf(z0-m), e1 = expf(z1-m), e2 = expf(z2-m), e3 = expf(z3-m);
        float S  = e0+e1+e2+e3;
        g_s[rr]  = e0/S + e1/S + e2/S + e3/S;

        #pragma unroll
        for (int no = 0; no < 4; no++){
            float o0 = HD[r][8+no*3+0], o1 = HD[r][8+no*3+1], o2 = HD[r][8+no*3+2];
            float st = sigmoidf_(ivt + o0)*2.0f - 1.0f;
            float sh = sigmoidf_(ivh + o1)*2.0f - 1.0f;
            float sw = sigmoidf_(ivw + o2)*2.0f - 1.0f;
            float ix = ((st + 1.0f)*32.0f - 1.0f)*0.5f;
            float iy = ((sh + 1.0f)*32.0f - 1.0f)*0.5f;
            float iz = ((sw + 1.0f)*8.0f  - 1.0f)*0.5f;
            int bidx = (rr*4 + no)*3;
            g_samp[bidx+0] = ix; g_samp[bidx+1] = iy; g_samp[bidx+2] = iz;
            float za = HD[r][20+no*2], zb = HD[r][21+no*2];
            g_wo[rr*4 + no] = 1.0f/(1.0f + expf(za - zb));
        }

        if (write_next){
            float d0 = sigmoidf_(ivt + HD[r][0]) * 7.0f;
            float d1 = sigmoidf_(ivh + HD[r][1]) * 31.0f;
            float d2 = sigmoidf_(ivw + HD[r][2]) * 31.0f;
            int ni = 1024*(int)rintf(d0) + 32*(int)rintf(d1) + (int)rintf(d2);
            out[FEAT_OUT_ELEMS + rr] = (float)ni;
        }
    }
}

// ============================================================
// Kernel 3: fill everything with beta[c]
// ============================================================
__global__ void fill_kernel(const float* __restrict__ beta, float4* __restrict__ out){
    int i = blockIdx.x * blockDim.x + threadIdx.x;      // 524288 float4s
    float b = __ldg(&beta[i >> 13]);
    out[i] = make_float4(b, b, b, b);
}

// ============================================================
// Kernel 4: 256 blocks x 512 threads, with warp-level corner dedup.
// ============================================================
__global__ void sample_ln_kernel(const float* __restrict__ feats,
                                 const float* __restrict__ gamma,
                                 const float* __restrict__ beta,
                                 float* __restrict__ out)
{
    int b  = blockIdx.x;           // row = l*64 + n
    int l  = b >> 6;
    int p  = flat_idx(b & 63);
    int tid = threadIdx.x;

    __shared__ int    uq[40];
    __shared__ float  uw[40];
    __shared__ int    s_nq;
    __shared__ float  partial[256];
    __shared__ float2 red[512];
    __shared__ float  s_scale, s_mu, s_rstd;

    if (tid < 32){
        const unsigned full = 0xffffffffu;
        int lane = tid;
        int no = lane >> 3, j = lane & 7;
        int gi = (b*4 + no)*3;
        float ix = g_samp[gi+0], iy = g_samp[gi+1], iz = g_samp[gi+2];
        float wo = g_wo[b*4 + no];
        float x0f = floorf(ix), y0f = floorf(iy), z0f = floorf(iz);
        int dx = j & 1, dy = (j >> 1) & 1, dz = j >> 2;
        int xi = (int)x0f + dx, yi = (int)y0f + dy, zi = (int)z0f + dz;
        float fx = ix - x0f, fy = iy - y0f, fz = iz - z0f;
        float w = (dx ? fx : 1.0f-fx) * (dy ? fy : 1.0f-fy) * (dz ? fz : 1.0f-fz) * wo;
        bool valid = (xi >= 0) & (xi < W_) & (yi >= 0) & (yi < H_) & (zi >= 0) & (zi < T_);
        if (!valid) w = 0.0f;
        int q = (min(max(zi,0),T_-1)*H_ + min(max(yi,0),H_-1))*W_ + min(max(xi,0),W_-1);

        // warp dedup: merge weights of identical q
        unsigned mask = __match_any_sync(full, q);
        float wsum = 0.0f;
        #pragma unroll
        for (int s2 = 0; s2 < 32; s2++){
            float wv = __shfl_sync(full, w, s2);
            int   qv = __shfl_sync(full, q, s2);
            if (qv == q) wsum += wv;
        }
        int leader = __ffs(mask) - 1;
        bool is_leader = (lane == leader);
        unsigned bal = __ballot_sync(full, is_leader);
        int pos = __popc(bal & ((1u << lane) - 1u));
        if (is_leader){ uq[pos] = q; uw[pos] = wsum; }
        __syncwarp();
        if (lane == 0){
            int nq = __popc(bal);
            bool found = false;
            for (int j2 = 0; j2 < nq; j2++){
                if (uq[j2] == p){ uw[j2] += 1.0f; found = true; break; }
            }
            if (!found){ uq[nq] = p; uw[nq] = 1.0f; nq++; }
            s_nq = nq;
            s_scale = g_s[b];
        }
    }
    __syncthreads();

    int c    = tid & 255;
    int half = tid >> 8;
    const float* fb = feats + (size_t)c*(THW_*L_) + l;

    float acc = 0.0f;
    int nq = s_nq;
    for (int j2 = half; j2 < nq; j2 += 2)
        acc = fmaf(uw[j2], __ldg(fb + (size_t)uq[j2]*L_), acc);

    if (half) partial[c] = acc;
    __syncthreads();

    float v = 0.0f;
    if (half == 0) v = (acc + partial[c]) * s_scale;

    red[tid] = make_float2(v, v*v);
    __syncthreads();
    for (int o = 256; o > 0; o >>= 1){
        if (tid < o){
            float2 a = red[tid], bb = red[tid+o];
            red[tid] = make_float2(a.x+bb.x, a.y+bb.y);
        }
        __syncthreads();
    }
    if (tid == 0){
        float mu  = red[0].x * (1.0f/256.0f);
        float var = red[0].y * (1.0f/256.0f) - mu*mu;
        s_mu = mu;
        s_rstd = rsqrtf(var + 1e-5f);
    }
    __syncthreads();

    if (half == 0){
        float o = (v - s_mu) * s_rstd * gamma[c] + beta[c];
        out[((size_t)c*THW_ + p)*L_ + l] = o;
    }
}

// ============================================================
extern "C" void kernel_launch(void* const* d_in, const int* in_sizes, int n_in,
                              void* d_out, int out_size)
{
    const float* feats = (const float*)d_in[0];
    const float* pos   = (const float*)d_in[1];
    const float* W1    = (const float*)d_in[2];
    const float* b1    = (const float*)d_in[3];
    const float* W2    = (const float*)d_in[4];
    const float* b2    = (const float*)d_in[5];
    const float* Wn    = (const float*)d_in[6];
    const float* bn    = (const float*)d_in[7];
    const float* Wl    = (const float*)d_in[8];
    const float* bl    = (const float*)d_in[9];
    const float* Woff  = (const float*)d_in[10];
    const float* boff  = (const float*)d_in[11];
    const float* Ww    = (const float*)d_in[12];
    const float* bw    = (const float*)d_in[13];
    const float* gamma = (const float*)d_in[14];
    const float* beta  = (const float*)d_in[15];
    float* out = (float*)d_out;

    int write_next = (out_size >= FEAT_OUT_ELEMS + NROWS) ? 1 : 0;

    static int smem_set = 0;
    if (!smem_set){
        cudaFuncSetAttribute(mlp_kernel, cudaFuncAttributeMaxDynamicSharedMemorySize,
                             MLP_SMEM_BYTES);
        smem_set = 1;
    }

    glob_kernel<<<256, 256>>>(feats);
    fill_kernel<<<2048, 256>>>(beta, (float4*)out);
    mlp_kernel<<<128, 256, MLP_SMEM_BYTES>>>(feats, pos, W1, b1, W2, b2, Wn, bn, Wl, bl,
                                             Woff, boff, Ww, bw, out, write_next);
    sample_ln_kernel<<<256, 512>>>(feats, gamma, beta, out);
}